// round 1
// baseline (speedup 1.0000x reference)
#include <cuda_runtime.h>
#include <math_constants.h>

// Problem constants
#define B_  64
#define C_  64
#define N_  325
#define T_  12
#define BT_ (B_ * T_)          // 768
#define NT_ (N_ * T_)          // 3900

// Scratch (no cudaMalloc allowed) — __device__ globals
__device__ float g_X1[BT_ * N_];    // g * softplus-pooled-half0 ^ l1   (row scale)
__device__ float g_X2[BT_ * N_];    // softplus-pooled-half1 ^ l2       (column factor)
__device__ float g_D2[N_ * N_];     // dist ^ (2*l3)

__device__ __forceinline__ float softplus_f(float x) {
    // matches jax.nn.softplus: max(x,0) + log1p(exp(-|x|))
    return fmaxf(x, 0.0f) + log1pf(expf(-fabsf(x)));
}

// ---------------------------------------------------------------------------
// Kernel 1: per (b, n, t) channel pooling + softplus + pow. Reads all of x
// (64 MB) once, coalesced over the contiguous (n*T) axis.
// ---------------------------------------------------------------------------
__global__ void __launch_bounds__(256) prep_kernel(
    const float* __restrict__ x,
    const float* __restrict__ l1p, const float* __restrict__ l2p,
    const float* __restrict__ Gp)
{
    int tid = blockIdx.x * blockDim.x + threadIdx.x;
    if (tid >= B_ * NT_) return;

    int b  = tid / NT_;
    int nt = tid - b * NT_;          // nt = n*T + t (contiguous in memory)

    const float* xb = x + (size_t)b * C_ * NT_ + nt;

    float s0 = 0.0f, s1 = 0.0f;
#pragma unroll
    for (int c = 0; c < 32; c++) s0 += xb[(size_t)c * NT_];
#pragma unroll
    for (int c = 32; c < 64; c++) s1 += xb[(size_t)c * NT_];

    float v1 = softplus_f(s0 * (1.0f / 32.0f)) + 1.0f;   // >= 1
    float v2 = softplus_f(s1 * (1.0f / 32.0f)) + 1.0f;

    float l1 = softplus_f(l1p[0]);
    float l2 = softplus_f(l2p[0]);
    float g  = softplus_f(Gp[0]);

    int n = nt / T_;
    int t = nt - n * T_;
    int bt = b * T_ + t;

    g_X1[bt * N_ + n] = g * powf(v1, l1);
    g_X2[bt * N_ + n] = powf(v2, l2);
}

// ---------------------------------------------------------------------------
// Kernel 2: D2 = dist ^ (2*l3).  N*N = 105,625 elements, trivial.
// ---------------------------------------------------------------------------
__global__ void __launch_bounds__(256) dist2_kernel(
    const float* __restrict__ dist, const float* __restrict__ l3p)
{
    int tid = blockIdx.x * blockDim.x + threadIdx.x;
    if (tid >= N_ * N_) return;
    float tl3 = 2.0f * softplus_f(l3p[0]);
    g_D2[tid] = powf(dist[tid], tl3);
}

// ---------------------------------------------------------------------------
// Kernel 3: fused logits + row softmax, one warp per (bt, i) row.
// Row (325 floats) lives in registers -> single exp per element.
// blockDim = 256 (8 warps); grid = (BT_, ceil(N/8)).
// ---------------------------------------------------------------------------
#define WARPS_PER_BLOCK 8
#define NITER 11                      // ceil(325 / 32)

__global__ void __launch_bounds__(256) softmax_kernel(float* __restrict__ out)
{
    __shared__ float X2s[N_];

    int bt = blockIdx.x;

    // stage the X2 row for this bt into shared memory
    for (int j = threadIdx.x; j < N_; j += blockDim.x)
        X2s[j] = g_X2[bt * N_ + j];
    __syncthreads();

    int warp = threadIdx.x >> 5;
    int lane = threadIdx.x & 31;
    int i = blockIdx.y * WARPS_PER_BLOCK + warp;
    if (i >= N_) return;

    float s = g_X1[bt * N_ + i];                 // row scale (g * x1^l1), > 0
    const float* __restrict__ d2 = g_D2 + i * N_;

    float vals[NITER];
    float m = -CUDART_INF_F;
#pragma unroll
    for (int k = 0; k < NITER; k++) {
        int j = lane + 32 * k;
        float a = (j < N_) ? s * (X2s[j] * d2[j]) : -CUDART_INF_F;
        vals[k] = a;
        m = fmaxf(m, a);
    }
    // warp max-reduce
#pragma unroll
    for (int o = 16; o > 0; o >>= 1)
        m = fmaxf(m, __shfl_xor_sync(0xffffffffu, m, o));

    float sum = 0.0f;
#pragma unroll
    for (int k = 0; k < NITER; k++) {
        float e = __expf(vals[k] - m);           // invalid lanes: exp(-inf)=0
        vals[k] = e;
        sum += e;
    }
    // warp sum-reduce
#pragma unroll
    for (int o = 16; o > 0; o >>= 1)
        sum += __shfl_xor_sync(0xffffffffu, sum, o);

    float inv = __fdividef(1.0f, sum);

    float* __restrict__ orow = out + ((size_t)bt * N_ + i) * N_;
#pragma unroll
    for (int k = 0; k < NITER; k++) {
        int j = lane + 32 * k;
        if (j < N_) orow[j] = vals[k] * inv;
    }
}

// ---------------------------------------------------------------------------
// Launch
// inputs (metadata order): x, dist, lamda1, lamda2, lamda3, G
// output: float32 [B, T, N, N]
// ---------------------------------------------------------------------------
extern "C" void kernel_launch(void* const* d_in, const int* in_sizes, int n_in,
                              void* d_out, int out_size)
{
    const float* x    = (const float*)d_in[0];
    const float* dist = (const float*)d_in[1];
    const float* l1   = (const float*)d_in[2];
    const float* l2   = (const float*)d_in[3];
    const float* l3   = (const float*)d_in[4];
    const float* G    = (const float*)d_in[5];
    float* out = (float*)d_out;

    {
        int total = B_ * NT_;
        int threads = 256;
        int blocks = (total + threads - 1) / threads;
        prep_kernel<<<blocks, threads>>>(x, l1, l2, G);
    }
    {
        int total = N_ * N_;
        int threads = 256;
        int blocks = (total + threads - 1) / threads;
        dist2_kernel<<<blocks, threads>>>(dist, l3);
    }
    {
        dim3 grid(BT_, (N_ + WARPS_PER_BLOCK - 1) / WARPS_PER_BLOCK);
        softmax_kernel<<<grid, 256>>>(out);
    }
}

// round 2
// speedup vs baseline: 1.1083x; 1.1083x over previous
#include <cuda_runtime.h>
#include <math_constants.h>

// Problem constants
#define B_  64
#define C_  64
#define N_  325
#define T_  12
#define BT_ (B_ * T_)          // 768
#define NT_ (N_ * T_)          // 3900

// Scratch (no cudaMalloc allowed) — __device__ globals
__device__ float g_X1[BT_ * N_];    // g * softplus-pooled-half0 ^ l1   (row scale)
__device__ float g_X2[BT_ * N_];    // softplus-pooled-half1 ^ l2       (column factor)
__device__ float g_D2[N_ * N_];     // dist ^ (2*l3)

__device__ __forceinline__ float softplus_f(float x) {
    // matches jax.nn.softplus: max(x,0) + log1p(exp(-|x|))
    return fmaxf(x, 0.0f) + log1pf(expf(-fabsf(x)));
}

// ---------------------------------------------------------------------------
// Kernel 1 (fused prep + dist2):
//   blocks [0, PREP_BLOCKS)         : channel pool + softplus + pow, float4
//                                     over the contiguous nt axis (4 nt/thread)
//   blocks [PREP_BLOCKS, +DIST_BLK) : D2 = dist ^ (2*l3)
// ---------------------------------------------------------------------------
#define PREP_THREADS ((B_ * NT_) / 4)                    // 62400 (NT_ % 4 == 0)
#define PREP_BLOCKS  ((PREP_THREADS + 255) / 256)        // 244
#define DIST_BLOCKS  ((N_ * N_ + 255) / 256)             // 413

__global__ void __launch_bounds__(256) prep_all_kernel(
    const float* __restrict__ x,
    const float* __restrict__ dist,
    const float* __restrict__ l1p, const float* __restrict__ l2p,
    const float* __restrict__ l3p, const float* __restrict__ Gp)
{
    if (blockIdx.x < PREP_BLOCKS) {
        int tid = blockIdx.x * blockDim.x + threadIdx.x;
        if (tid >= PREP_THREADS) return;

        int b   = tid / (NT_ / 4);
        int nt0 = (tid - b * (NT_ / 4)) * 4;   // 16B aligned (nt0 % 4 == 0)

        const float4* xb4 = (const float4*)(x + (size_t)b * C_ * NT_ + nt0);
        const int str4 = NT_ / 4;              // float4 stride per channel

        float4 s0 = make_float4(0.f, 0.f, 0.f, 0.f);
        float4 s1 = make_float4(0.f, 0.f, 0.f, 0.f);
#pragma unroll
        for (int c = 0; c < 32; c++) {
            float4 v = xb4[c * str4];
            s0.x += v.x; s0.y += v.y; s0.z += v.z; s0.w += v.w;
        }
#pragma unroll
        for (int c = 32; c < 64; c++) {
            float4 v = xb4[c * str4];
            s1.x += v.x; s1.y += v.y; s1.z += v.z; s1.w += v.w;
        }

        float l1 = softplus_f(l1p[0]);
        float l2 = softplus_f(l2p[0]);
        float g  = softplus_f(Gp[0]);

        float a0[4] = {s0.x, s0.y, s0.z, s0.w};
        float a1[4] = {s1.x, s1.y, s1.z, s1.w};
#pragma unroll
        for (int q = 0; q < 4; q++) {
            int nt = nt0 + q;
            int n  = nt / T_;
            int t  = nt - n * T_;
            int bt = b * T_ + t;
            float v1 = softplus_f(a0[q] * (1.0f / 32.0f)) + 1.0f;
            float v2 = softplus_f(a1[q] * (1.0f / 32.0f)) + 1.0f;
            g_X1[bt * N_ + n] = g * powf(v1, l1);
            g_X2[bt * N_ + n] = powf(v2, l2);
        }
    } else {
        int tid = (blockIdx.x - PREP_BLOCKS) * blockDim.x + threadIdx.x;
        if (tid >= N_ * N_) return;
        float tl3 = 2.0f * softplus_f(l3p[0]);
        g_D2[tid] = powf(dist[tid], tl3);
    }
}

// ---------------------------------------------------------------------------
// Kernel 2: fused logits + row softmax, tiled 8 i-rows x 8 bt per block.
// D2 rows staged in smem once and cached in registers per warp; X2 rows for
// the 8 bt staged in smem. Cuts D2 L2 read traffic 8x vs one-bt-per-block.
// ---------------------------------------------------------------------------
#define IPB 8                         // i rows per block (one per warp)
#define GBT 8                         // bt values per block
#define NITER 11                      // ceil(325 / 32)

__global__ void __launch_bounds__(256) softmax_kernel(float* __restrict__ out)
{
    __shared__ float D2s[IPB][N_];    // 10400 B
    __shared__ float X2s[GBT][N_];    // 10400 B
    __shared__ float X1s[GBT][IPB];   // 256 B

    const int ib  = blockIdx.x * IPB;
    const int btb = blockIdx.y * GBT;

    // stage D2 rows for i in [ib, ib+8)
    for (int idx = threadIdx.x; idx < IPB * N_; idx += blockDim.x) {
        int r = idx / N_;
        int j = idx - r * N_;
        int i = ib + r;
        D2s[r][j] = (i < N_) ? g_D2[i * N_ + j] : 0.0f;
    }
    // stage X2 rows for bt in [btb, btb+8)
    for (int idx = threadIdx.x; idx < GBT * N_; idx += blockDim.x) {
        int r = idx / N_;
        int j = idx - r * N_;
        X2s[r][j] = g_X2[(btb + r) * N_ + j];
    }
    // stage X1 scalars
    if (threadIdx.x < GBT * IPB) {
        int gq = threadIdx.x / IPB;
        int r  = threadIdx.x - gq * IPB;
        int i  = ib + r;
        X1s[gq][r] = (i < N_) ? g_X1[(btb + gq) * N_ + i] : 0.0f;
    }
    __syncthreads();

    const int warp = threadIdx.x >> 5;
    const int lane = threadIdx.x & 31;
    const int i = ib + warp;
    if (i >= N_) return;

    // cache my D2 row in registers
    float d2v[NITER];
#pragma unroll
    for (int k = 0; k < NITER; k++) {
        int j = lane + 32 * k;
        d2v[k] = (j < N_) ? D2s[warp][j] : 0.0f;
    }

#pragma unroll 1
    for (int gq = 0; gq < GBT; gq++) {
        const int bt = btb + gq;
        const float s = X1s[gq][warp];           // g * x1^l1, > 0

        float vals[NITER];
        float m = -CUDART_INF_F;
#pragma unroll
        for (int k = 0; k < NITER; k++) {
            int j = lane + 32 * k;
            float a = (j < N_) ? s * (X2s[gq][j] * d2v[k]) : -CUDART_INF_F;
            vals[k] = a;
            m = fmaxf(m, a);
        }
#pragma unroll
        for (int o = 16; o > 0; o >>= 1)
            m = fmaxf(m, __shfl_xor_sync(0xffffffffu, m, o));

        float sum = 0.0f;
#pragma unroll
        for (int k = 0; k < NITER; k++) {
            float e = __expf(vals[k] - m);       // invalid lanes: exp(-inf)=0
            vals[k] = e;
            sum += e;
        }
#pragma unroll
        for (int o = 16; o > 0; o >>= 1)
            sum += __shfl_xor_sync(0xffffffffu, sum, o);

        float inv = __fdividef(1.0f, sum);

        float* __restrict__ orow = out + ((size_t)bt * N_ + i) * N_;
#pragma unroll
        for (int k = 0; k < NITER; k++) {
            int j = lane + 32 * k;
            if (j < N_) orow[j] = vals[k] * inv;
        }
    }
}

// ---------------------------------------------------------------------------
// Launch
// inputs (metadata order): x, dist, lamda1, lamda2, lamda3, G
// output: float32 [B, T, N, N]
// ---------------------------------------------------------------------------
extern "C" void kernel_launch(void* const* d_in, const int* in_sizes, int n_in,
                              void* d_out, int out_size)
{
    const float* x    = (const float*)d_in[0];
    const float* dist = (const float*)d_in[1];
    const float* l1   = (const float*)d_in[2];
    const float* l2   = (const float*)d_in[3];
    const float* l3   = (const float*)d_in[4];
    const float* G    = (const float*)d_in[5];
    float* out = (float*)d_out;

    prep_all_kernel<<<PREP_BLOCKS + DIST_BLOCKS, 256>>>(x, dist, l1, l2, l3, G);

    dim3 grid((N_ + IPB - 1) / IPB, BT_ / GBT);   // (41, 96)
    softmax_kernel<<<grid, 256>>>(out);
}